// round 9
// baseline (speedup 1.0000x reference)
#include <cuda_runtime.h>

#define BATCH 4096
#define HDIM  128
#define G3    384
#define NL    4
#define TENC  64
#define TTGT  100
#define TSTEPS 163
#define BC    16
#define NCTA  256
#define NTHR  256
#define NMAT  14
#define MS    (G3 * HDIM)      // 49152 elements per big matrix

typedef unsigned long long u64;

// output layout: concatenated flattened outputs, fp32
// (decoder_output, dec_hidden, encoder_output, enc_hidden, loss)
static constexpr size_t OFF_DECOUT = 0;
static constexpr size_t OFF_DECH   = (size_t)BATCH * TTGT * 4;                    // 1,638,400
static constexpr size_t OFF_ENCOUT = OFF_DECH + (size_t)NL * BATCH * HDIM;        // 3,735,552
static constexpr size_t OFF_ENCH   = OFF_ENCOUT + (size_t)BATCH * TENC * HDIM;    // 37,289,984
static constexpr size_t OFF_LOSS   = OFF_ENCH + (size_t)NL * BATCH * HDIM;        // 39,387,136

__device__ float g_lossPart[NCTA];

// Permuted weight scratch. Layout per matrix (float index):
//   e = ((i*12) + g*4 + jj)*128 + jt*4 + c
// where i = k0/4 (0..31), g = gate (0..2), jj = row-within-quad (0..3),
// jt = j-quad (0..31), c = k-within-chunk (0..3).
// A warp's LDG.128 for fixed (i,g,jj) covers its 4 consecutive jt -> 64B
// contiguous, fully used, single 128B line.
__device__ __align__(16) float g_wpk[NMAT][MS];       // 2.75 MB
__device__ __align__(16) float g_l1pk[HDIM * HDIM];   // 64 KB, same idea with g==0 only

// single dynamic smem region (floats), total 12288 floats = 49152 B = 48 KB exactly
//   [0, 8192)      h[4][16][128]   (16B-chunk XOR-swizzled per row, see swz())
//   [8192, 8704)   br[4][128]  = bih_r + bhh_r
//   [8704, 9216)   bz[4][128]  = bih_z + bhh_z
//   [9216, 9728)   bin[4][128] = bih_n
//   [9728,10240)   bhn[4][128] = bhh_n
//   [10240,12288)  o1[16][128]  (decoder lin1 staging; reused as reduction scratch at end)
#define SM_H    0
#define SM_BR   8192
#define SM_BZ   8704
#define SM_BIN  9216
#define SM_BHN  9728
#define SM_O1   10240
#define SM_RED  10240
#define SM_FLOATS 12288

// swizzle: 16B chunk index c within a 128-float row m maps to c ^ (m>>1).
__device__ __forceinline__ int swz(int row, int k0) {   // k0 multiple of 4
    return (((k0 >> 2) ^ (row >> 1)) & 31) << 2;
}
__device__ __forceinline__ int swz_j(int row, int j) {  // scalar j
    return (((((j >> 2) ^ (row >> 1)) & 31) << 2) | (j & 3));
}

__device__ __forceinline__ float sigm(float x)  { return 1.0f / (1.0f + __expf(-x)); }
__device__ __forceinline__ float tanha(float x) { return 1.0f - 2.0f / (1.0f + __expf(2.0f * x)); }

__device__ __forceinline__ void pfma(u64& d, u64 a, u64 b) {
    asm("fma.rn.f32x2 %0, %1, %2, %0;" : "+l"(d) : "l"(a), "l"(b));
}
__device__ __forceinline__ float hsum2(u64 v) {
    float lo, hi;
    asm("mov.b64 {%0, %1}, %2;" : "=f"(lo), "=f"(hi) : "l"(v));
    return lo + hi;
}

// ---------------- prep: permute weights into coalesced-stream layout ----------------
__global__ void prep_kernel(
    const float* __restrict__ e_whh0, const float* __restrict__ e_wih,
    const float* __restrict__ e_whh,  const float* __restrict__ d_whh0,
    const float* __restrict__ d_wih,  const float* __restrict__ d_whh,
    const float* __restrict__ l1w)
{
    int idx = blockIdx.x * blockDim.x + threadIdx.x;
    if (idx < NMAT * MS) {
        int m = idx / MS, e = idx % MS;
        int c  = e & 3;
        int jt = (e >> 2) & 31;
        int gj = (e >> 7) % 12;          // g*4+jj
        int i  = e / (12 * 128);         // k0/4
        int g  = gj >> 2, jj = gj & 3;
        int row = g * HDIM + jt * 4 + jj;
        int col = i * 4 + c;
        const float* src;
        if      (m == 0)  src = e_whh0;
        else if (m <= 3)  src = e_wih + (m - 1) * MS;
        else if (m <= 6)  src = e_whh + (m - 4) * MS;
        else if (m == 7)  src = d_whh0;
        else if (m <= 10) src = d_wih + (m - 8) * MS;
        else              src = d_whh + (m - 11) * MS;
        g_wpk[m][e] = src[row * HDIM + col];
    } else if (idx < NMAT * MS + HDIM * HDIM) {
        int e = idx - NMAT * MS;
        int c = e & 3, jt = (e >> 2) & 31, jj = (e >> 7) & 3, i = e >> 9;
        g_l1pk[e] = l1w[(jt * 4 + jj) * HDIM + i * 4 + c];
    }
}

// packed 3-gate GEMM from permuted weights:
// p{A,B,C}[bb][jj] += h[b0+bb][k] * W[(jt*4+jj)+{0,128,256}][k]
__device__ __forceinline__ void accum3_pk(
    u64 (&aA)[2][4], u64 (&aB)[2][4], u64 (&aC)[2][4],
    const float4* __restrict__ Wp, const float* __restrict__ hbase,
    int b0, int jt)
{
#pragma unroll 2
    for (int i = 0; i < 32; ++i) {
        const int k0 = i * 4;
        longlong2 v0 = *(const longlong2*)(hbase + (b0    ) * HDIM + swz(b0,     k0));
        longlong2 v1 = *(const longlong2*)(hbase + (b0 + 1) * HDIM + swz(b0 + 1, k0));
        const float4* p = Wp + i * (12 * 32) + jt;
#pragma unroll
        for (int jj = 0; jj < 4; ++jj) {
            longlong2 w0 = __ldg((const longlong2*)(p + (0 * 4 + jj) * 32));
            longlong2 w1 = __ldg((const longlong2*)(p + (1 * 4 + jj) * 32));
            longlong2 w2 = __ldg((const longlong2*)(p + (2 * 4 + jj) * 32));
            pfma(aA[0][jj], (u64)v0.x, (u64)w0.x); pfma(aA[0][jj], (u64)v0.y, (u64)w0.y);
            pfma(aA[1][jj], (u64)v1.x, (u64)w0.x); pfma(aA[1][jj], (u64)v1.y, (u64)w0.y);
            pfma(aB[0][jj], (u64)v0.x, (u64)w1.x); pfma(aB[0][jj], (u64)v0.y, (u64)w1.y);
            pfma(aB[1][jj], (u64)v1.x, (u64)w1.x); pfma(aB[1][jj], (u64)v1.y, (u64)w1.y);
            pfma(aC[0][jj], (u64)v0.x, (u64)w2.x); pfma(aC[0][jj], (u64)v0.y, (u64)w2.y);
            pfma(aC[1][jj], (u64)v1.x, (u64)w2.x); pfma(aC[1][jj], (u64)v1.y, (u64)w2.y);
        }
    }
}

// packed single GEMM (lin1) from permuted l1w
__device__ __forceinline__ void accum1_pk(
    u64 (&aA)[2][4],
    const float* __restrict__ hbase, int b0, int jt)
{
    const float4* Wp = (const float4*)g_l1pk;
#pragma unroll 2
    for (int i = 0; i < 32; ++i) {
        const int k0 = i * 4;
        longlong2 v0 = *(const longlong2*)(hbase + (b0    ) * HDIM + swz(b0,     k0));
        longlong2 v1 = *(const longlong2*)(hbase + (b0 + 1) * HDIM + swz(b0 + 1, k0));
        const float4* p = Wp + i * (4 * 32) + jt;
#pragma unroll
        for (int jj = 0; jj < 4; ++jj) {
            longlong2 w = __ldg((const longlong2*)(p + jj * 32));
            pfma(aA[0][jj], (u64)v0.x, (u64)w.x); pfma(aA[0][jj], (u64)v0.y, (u64)w.y);
            pfma(aA[1][jj], (u64)v1.x, (u64)w.x); pfma(aA[1][jj], (u64)v1.y, (u64)w.y);
        }
    }
}

__device__ __forceinline__ void load_biases(float* SH,
                                            const float* __restrict__ bih,
                                            const float* __restrict__ bhh,
                                            int tid)
{
    for (int i = tid; i < NL * HDIM; i += NTHR) {
        int l = i >> 7;
        int j = i & 127;
        SH[SM_BR  + i] = bih[l * G3 + j]            + bhh[l * G3 + j];
        SH[SM_BZ  + i] = bih[l * G3 + HDIM + j]     + bhh[l * G3 + HDIM + j];
        SH[SM_BIN + i] = bih[l * G3 + 2 * HDIM + j];
        SH[SM_BHN + i] = bhh[l * G3 + 2 * HDIM + j];
    }
}

__global__ void __launch_bounds__(NTHR, 2)
gru_seq2seq_kernel(
    const float* __restrict__ inp,      // (4096, 64, 4)
    const float* __restrict__ tgt,      // (4096, 100, 4)
    const float* __restrict__ e_wih0,   // (384, 4)
    const float* __restrict__ d_wih0,
    const float* __restrict__ e_bih,    // (4, 384)
    const float* __restrict__ e_bhh,
    const float* __restrict__ d_bih,
    const float* __restrict__ d_bhh,
    const float* __restrict__ l1b,      // (128)
    const float* __restrict__ l2w,      // (4, 128)
    const float* __restrict__ l2b,      // (4)
    float* __restrict__ out)
{
    extern __shared__ __align__(16) float SH[];

    const int tid = threadIdx.x;
    const int cta = blockIdx.x;
    const int bt  = tid & 7;
    const int jt  = tid >> 3;          // 0..31, j0 = jt*4
    const int b0  = bt * 2;            // local batch-row base (covers b0, b0+1)
    const int j0  = jt * 4;
    const size_t bg0 = (size_t)cta * BC;

    // init: zero hidden, load encoder biases
    for (int i = tid; i < NL * BC * HDIM; i += NTHR) SH[SM_H + i] = 0.0f;
    load_biases(SH, e_bih, e_bhh, tid);
    __syncthreads();

    float lossAcc = 0.0f;

    for (int t = 0; t < TSTEPS; ++t) {
        const bool enc = (t < TENC);

        if (t == TENC) {
            // snapshot enc_hidden (L, B, H) — de-swizzle
            for (int i = tid; i < NL * BC * HDIM; i += NTHR) {
                int l = i >> 11;
                int b = (i >> 7) & 15;
                int j = i & 127;
                out[OFF_ENCH + (size_t)l * BATCH * HDIM + (bg0 + b) * HDIM + j] =
                    SH[SM_H + l * BC * HDIM + b * HDIM + swz_j(b, j)];
            }
            load_biases(SH, d_bih, d_bhh, tid);
            if (tid < BC * 4) {
                int b = tid >> 2, e = tid & 3;
                out[OFF_DECOUT + (bg0 + b) * (TTGT * 4) + e] = inp[(bg0 + b) * (TENC * 4) + e];
            }
            __syncthreads();
        }

        const float* wih0 = enc ? e_wih0 : d_wih0;
        const int mbase = enc ? 0 : 7;   // matrix index base in g_wpk

        for (int l = 0; l < NL; ++l) {
            u64 pR[2][4]  = {};
            u64 pZ[2][4]  = {};
            u64 pIN[2][4] = {};
            u64 pHN[2][4] = {};

            if (l == 0) {
                // packed input GEMM with E=4 input (raw wih0; tiny)
                const float* xrow;
                int xstr;
                if (enc)              { xrow = inp + (size_t)t * 4;            xstr = TENC * 4; }
                else if (t == TENC)   { xrow = inp;                            xstr = TENC * 4; }
                else                  { xrow = tgt + (size_t)(t - TENC) * 4;   xstr = TTGT * 4; }

                longlong2 xv0 = __ldg((const longlong2*)(xrow + (bg0 + b0)     * xstr));
                longlong2 xv1 = __ldg((const longlong2*)(xrow + (bg0 + b0 + 1) * xstr));
#pragma unroll
                for (int jj = 0; jj < 4; ++jj) {
                    int r = j0 + jj;
                    longlong2 w0 = __ldg((const longlong2*)(wih0 + r * 4));
                    longlong2 w1 = __ldg((const longlong2*)(wih0 + (r +     HDIM) * 4));
                    longlong2 w2 = __ldg((const longlong2*)(wih0 + (r + 2 * HDIM) * 4));
                    pfma(pR[0][jj],  (u64)xv0.x, (u64)w0.x); pfma(pR[0][jj],  (u64)xv0.y, (u64)w0.y);
                    pfma(pR[1][jj],  (u64)xv1.x, (u64)w0.x); pfma(pR[1][jj],  (u64)xv1.y, (u64)w0.y);
                    pfma(pZ[0][jj],  (u64)xv0.x, (u64)w1.x); pfma(pZ[0][jj],  (u64)xv0.y, (u64)w1.y);
                    pfma(pZ[1][jj],  (u64)xv1.x, (u64)w1.x); pfma(pZ[1][jj],  (u64)xv1.y, (u64)w1.y);
                    pfma(pIN[0][jj], (u64)xv0.x, (u64)w2.x); pfma(pIN[0][jj], (u64)xv0.y, (u64)w2.y);
                    pfma(pIN[1][jj], (u64)xv1.x, (u64)w2.x); pfma(pIN[1][jj], (u64)xv1.y, (u64)w2.y);
                }
                accum3_pk(pR, pZ, pHN, (const float4*)g_wpk[mbase + 0],
                          SH + SM_H + 0 * BC * HDIM, b0, jt);
            } else {
                const float4* wih = (const float4*)g_wpk[mbase + 1 + (l - 1)];      // wih layers 1..3
                const float4* whh = (const float4*)g_wpk[mbase + 4 + (l - 1)];      // whh layers 1..3
                accum3_pk(pR, pZ, pIN, wih, SH + SM_H + (l - 1) * BC * HDIM, b0, jt); // x = h[l-1] (new)
                accum3_pk(pR, pZ, pHN, whh, SH + SM_H + l * BC * HDIM, b0, jt);       // h = h[l] (old)
            }

            __syncthreads();   // all reads of h[l] done before overwrite

            // gate phase
            {
                float* hl = SH + SM_H + l * BC * HDIM;
                const bool wrEnc = (l == NL - 1) && enc;
                float bR4[4], bZ4[4], bI4[4], bH4[4];
#pragma unroll
                for (int jj = 0; jj < 4; ++jj) {
                    bR4[jj] = SH[SM_BR  + l * HDIM + j0 + jj];
                    bZ4[jj] = SH[SM_BZ  + l * HDIM + j0 + jj];
                    bI4[jj] = SH[SM_BIN + l * HDIM + j0 + jj];
                    bH4[jj] = SH[SM_BHN + l * HDIM + j0 + jj];
                }
#pragma unroll
                for (int bb = 0; bb < 2; ++bb) {
                    int row = b0 + bb;
                    float* hrow = hl + row * HDIM + swz(row, j0);
                    float4 hold = *(const float4*)hrow;
                    float4 hnew;
#pragma unroll
                    for (int jj = 0; jj < 4; ++jj) {
                        float r = sigm(bR4[jj] + hsum2(pR[bb][jj]));
                        float z = sigm(bZ4[jj] + hsum2(pZ[bb][jj]));
                        float n = tanha(bI4[jj] + hsum2(pIN[bb][jj]) +
                                        r * (bH4[jj] + hsum2(pHN[bb][jj])));
                        float ho = (&hold.x)[jj];
                        (&hnew.x)[jj] = n + z * (ho - n);
                    }
                    *(float4*)hrow = hnew;
                    if (wrEnc) {
                        *(float4*)(out + OFF_ENCOUT +
                                   (bg0 + row) * (size_t)(TENC * HDIM) +
                                   (size_t)t * HDIM + j0) = hnew;
                    }
                }
            }
            __syncthreads();   // h[l] new values visible before next layer reads
        }

        if (!enc) {
            const int td = t - TENC;
            // lin1 + relu into o1 staging (o1 unswizzled)
            u64 p1[2][4] = {};
            accum1_pk(p1, SH + SM_H + (NL - 1) * BC * HDIM, b0, jt);
#pragma unroll
            for (int bb = 0; bb < 2; ++bb)
#pragma unroll
                for (int jj = 0; jj < 4; ++jj) {
                    float v = __ldg(l1b + j0 + jj) + hsum2(p1[bb][jj]);
                    SH[SM_O1 + (b0 + bb) * HDIM + j0 + jj] = fmaxf(v, 0.0f);
                }
            __syncthreads();

            // lin2 + output + loss (64 threads, one (b,e) each)
            if (tid < BC * 4) {
                int b = tid >> 2, e = tid & 3;
                float acc = __ldg(l2b + e);
                const float* orow = SH + SM_O1 + b * HDIM;
                const float* wrow = l2w + e * HDIM;
#pragma unroll 8
                for (int k0 = 0; k0 < HDIM; k0 += 4) {
                    float4 a4 = *(const float4*)(orow + k0);
                    float4 w4 = __ldg((const float4*)(wrow + k0));
                    acc += a4.x * w4.x + a4.y * w4.y + a4.z * w4.z + a4.w * w4.w;
                }
                size_t gb = bg0 + b;
                out[OFF_DECOUT + gb * (TTGT * 4) + (size_t)(td + 1) * 4 + e] = acc;
                float y = __ldg(tgt + gb * (TTGT * 4) + (size_t)(td + 1) * 4 + e);
                float d = acc - y;
                lossAcc += d * d;
            }
        }
    }

    __syncthreads();
    // dec_hidden (final h) -> out — de-swizzle
    for (int i = tid; i < NL * BC * HDIM; i += NTHR) {
        int l = i >> 11;
        int b = (i >> 7) & 15;
        int j = i & 127;
        out[OFF_DECH + (size_t)l * BATCH * HDIM + (bg0 + b) * HDIM + j] =
            SH[SM_H + l * BC * HDIM + b * HDIM + swz_j(b, j)];
    }

    // deterministic CTA loss partial
    __syncthreads();
    SH[SM_RED + tid] = lossAcc;
    __syncthreads();
    for (int o = NTHR / 2; o > 0; o >>= 1) {
        if (tid < o) SH[SM_RED + tid] += SH[SM_RED + tid + o];
        __syncthreads();
    }
    if (tid == 0) g_lossPart[cta] = SH[SM_RED];
}

__global__ void loss_reduce_kernel(float* __restrict__ out)
{
    __shared__ float s[NCTA];
    int tid = threadIdx.x;
    s[tid] = g_lossPart[tid];
    __syncthreads();
    for (int o = NCTA / 2; o > 0; o >>= 1) {
        if (tid < o) s[tid] += s[tid + o];
        __syncthreads();
    }
    if (tid == 0) out[OFF_LOSS] = s[0] * (1.0f / (float)(BATCH * 4));
}

extern "C" void kernel_launch(void* const* d_in, const int* in_sizes, int n_in,
                              void* d_out, int out_size)
{
    const float* inp    = (const float*)d_in[0];
    const float* tgt    = (const float*)d_in[1];
    const float* e_wih0 = (const float*)d_in[2];
    const float* e_whh0 = (const float*)d_in[3];
    const float* e_wih  = (const float*)d_in[4];
    const float* e_whh  = (const float*)d_in[5];
    const float* e_bih  = (const float*)d_in[6];
    const float* e_bhh  = (const float*)d_in[7];
    const float* d_wih0 = (const float*)d_in[8];
    const float* d_whh0 = (const float*)d_in[9];
    const float* d_wih  = (const float*)d_in[10];
    const float* d_whh  = (const float*)d_in[11];
    const float* d_bih  = (const float*)d_in[12];
    const float* d_bhh  = (const float*)d_in[13];
    const float* l1w    = (const float*)d_in[14];
    const float* l1b    = (const float*)d_in[15];
    const float* l2w    = (const float*)d_in[16];
    const float* l2b    = (const float*)d_in[17];
    float* out = (float*)d_out;

    const int prep_total = NMAT * MS + HDIM * HDIM;
    prep_kernel<<<(prep_total + 255) / 256, 256>>>(
        e_whh0, e_wih, e_whh, d_whh0, d_wih, d_whh, l1w);

    gru_seq2seq_kernel<<<NCTA, NTHR, SM_FLOATS * sizeof(float)>>>(
        inp, tgt, e_wih0, d_wih0, e_bih, e_bhh, d_bih, d_bhh,
        l1b, l2w, l2b, out);
    loss_reduce_kernel<<<1, NCTA>>>(out);
}